// round 12
// baseline (speedup 1.0000x reference)
#include <cuda_runtime.h>
#include <cuda_fp16.h>
#include <math.h>
#include <cstdint>

#define T_  512
#define B_  256
#define D_  512
#define H_  512
#define H2_ (2*H_)
#define H3_ (3*H_)

#define SNBLK 64
#define SNTHR 512

typedef unsigned long long ull;

// ===========================================================================
// Global scratch
// ===========================================================================
__device__ float g_gi[(size_t)T_ * B_ * H3_];          // gi = ins @ Wi + bi
__device__ float g_mask[T_ * B_];
__device__ __half g_ah[(size_t)T_ * B_ * D_];          // ins fp16 [m][k]
__device__ __half g_bh[(size_t)H3_ * D_];              // Wi^T fp16 [n][k]
__device__ unsigned g_flag[8 * 16 * 32];               // [group][hti] step flags

// ===========================================================================
// helpers
// ===========================================================================
__device__ __forceinline__ uint32_t smem_u32(const void* p) {
    uint32_t a;
    asm("{ .reg .u64 t; cvta.to.shared.u64 t, %1; cvt.u32.u64 %0, t; }"
        : "=r"(a) : "l"(p));
    return a;
}

#define LDSM4(R, A) \
    asm volatile("ldmatrix.sync.aligned.m8n8.x4.shared.b16 {%0,%1,%2,%3}, [%4];" \
        : "=r"((R)[0]), "=r"((R)[1]), "=r"((R)[2]), "=r"((R)[3]) : "r"(A))
#define LDSM2(R, A) \
    asm volatile("ldmatrix.sync.aligned.m8n8.x2.shared.b16 {%0,%1}, [%2];" \
        : "=r"((R)[0]), "=r"((R)[1]) : "r"(A))

__device__ __forceinline__ void mma4(float* c, const unsigned* a,
                                     unsigned b0, unsigned b1) {
    asm volatile(
        "mma.sync.aligned.m16n8k16.row.col.f32.f16.f16.f32 "
        "{%0,%1,%2,%3}, {%4,%5,%6,%7}, {%8,%9}, {%0,%1,%2,%3};"
        : "+f"(c[0]), "+f"(c[1]), "+f"(c[2]), "+f"(c[3])
        : "r"(a[0]), "r"(a[1]), "r"(a[2]), "r"(a[3]), "r"(b0), "r"(b1));
}

__device__ __forceinline__ ull cvt4h(float4 v) {
    __half2 a = __floats2half2_rn(v.x, v.y);
    __half2 b = __floats2half2_rn(v.z, v.w);
    ull r;
    asm("mov.b64 %0, {%1, %2};" : "=l"(r)
        : "r"(*(unsigned*)&a), "r"(*(unsigned*)&b));
    return r;
}

// ===========================================================================
// Reset-mask prep + flag reset (every call — graph replay safe)
// ===========================================================================
__global__ void prep_mask_kernel(const void* __restrict__ resets)
{
    const int N = T_ * B_;
    for (int i = threadIdx.x; i < 8 * 16 * 32; i += blockDim.x)
        g_flag[i] = 0;
    const unsigned char* b8 = (const unsigned char*)resets;
    int found = 0;
    for (int i = threadIdx.x; i < N; i += blockDim.x)
        if ((i & 3) && b8[i] == 1) found = 1;
    int is_byte = __syncthreads_or(found);
    if (is_byte) {
        for (int i = threadIdx.x; i < N; i += blockDim.x)
            g_mask[i] = b8[i] ? 0.0f : 1.0f;
    } else {
        const unsigned int* w32 = (const unsigned int*)resets;
        for (int i = threadIdx.x; i < N; i += blockDim.x)
            g_mask[i] = w32[i] ? 0.0f : 1.0f;
    }
}

// ===========================================================================
// fp16 conversion for A (ins) and B (Wi^T)
// ===========================================================================
__global__ void conv_ab_kernel(const float* __restrict__ ins,
                               const float* __restrict__ Wi)
{
    const size_t totalA = (size_t)T_ * B_ * D_ / 8;
    const size_t totalB = (size_t)H3_ * (D_ / 8);
    const size_t total = totalA + totalB;
    for (size_t i = (size_t)blockIdx.x * blockDim.x + threadIdx.x;
         i < total; i += (size_t)gridDim.x * blockDim.x) {
        if (i < totalA) {
            size_t base = i * 8;
            float4 a = *(const float4*)(ins + base);
            float4 b = *(const float4*)(ins + base + 4);
            *(ull*)&g_ah[base] = cvt4h(a);
            *(ull*)&g_ah[base + 4] = cvt4h(b);
        } else {
            size_t j = i - totalA;
            int n = (int)(j % H3_);
            int k8 = (int)(j / H3_) * 8;
            float4 a, b;
            a.x = Wi[(size_t)(k8+0)*H3_ + n]; a.y = Wi[(size_t)(k8+1)*H3_ + n];
            a.z = Wi[(size_t)(k8+2)*H3_ + n]; a.w = Wi[(size_t)(k8+3)*H3_ + n];
            b.x = Wi[(size_t)(k8+4)*H3_ + n]; b.y = Wi[(size_t)(k8+5)*H3_ + n];
            b.z = Wi[(size_t)(k8+6)*H3_ + n]; b.w = Wi[(size_t)(k8+7)*H3_ + n];
            size_t o = (size_t)n * D_ + k8;
            *(ull*)&g_bh[o] = cvt4h(a);
            *(ull*)&g_bh[o + 4] = cvt4h(b);
        }
    }
}

// ===========================================================================
// gi GEMM (unchanged — proven)
// ===========================================================================
#define SAK 40

__global__ __launch_bounds__(256)
void gi_gemm_kernel(const float* __restrict__ bias, float* __restrict__ C)
{
    __shared__ __half sAh[128 * SAK];
    __shared__ __half sBh[128 * SAK];

    const int tid = threadIdx.x;
    const int n0  = blockIdx.x * 128;
    const int m0  = blockIdx.y * 128;
    const int wid = tid >> 5, lane = tid & 31;
    const int wm = (wid & 1) * 64;
    const int wn = (wid >> 1) * 32;
    const int g  = lane >> 2;
    const int tg = lane & 3;

    const int sr = tid >> 1, sk = (tid & 1) * 16;
    const __half* pAh = g_ah + (size_t)(m0 + sr) * D_ + sk;
    const __half* pBh = g_bh + (size_t)(n0 + sr) * D_ + sk;

    const uint32_t aH = smem_u32(sAh) + (((wm + (lane & 15)) * SAK) +
                        ((lane & 16) ? 8 : 0)) * 2;
    const uint32_t bH = smem_u32(sBh) + (((wn + (lane & 7) +
                        ((lane & 16) ? 8 : 0)) * SAK) +
                        ((lane & 8) ? 8 : 0)) * 2;
    const int mstep = 16 * SAK * 2;
    const int nstep = 16 * SAK * 2;

    float acc[4][4][4];
    #pragma unroll
    for (int i = 0; i < 4; i++)
        #pragma unroll
        for (int j = 0; j < 4; j++)
            #pragma unroll
            for (int q = 0; q < 4; q++) acc[i][j][q] = 0.0f;

    uint4 rah0, rah1, rbh0, rbh1;
    rah0 = *(const uint4*)(pAh);     rah1 = *(const uint4*)(pAh + 8);
    rbh0 = *(const uint4*)(pBh);     rbh1 = *(const uint4*)(pBh + 8);

    for (int kc = 0; kc < D_ / 32; kc++) {
        __syncthreads();
        *(uint4*)&sAh[sr * SAK + sk] = rah0;  *(uint4*)&sAh[sr * SAK + sk + 8] = rah1;
        *(uint4*)&sBh[sr * SAK + sk] = rbh0;  *(uint4*)&sBh[sr * SAK + sk + 8] = rbh1;
        __syncthreads();

        if (kc + 1 < D_ / 32) {
            int k0 = (kc + 1) * 32;
            rah0 = *(const uint4*)(pAh + k0);  rah1 = *(const uint4*)(pAh + k0 + 8);
            rbh0 = *(const uint4*)(pBh + k0);  rbh1 = *(const uint4*)(pBh + k0 + 8);
        }

        #pragma unroll
        for (int ks = 0; ks < 2; ks++) {
            const int k2 = ks * 32;
            unsigned bh01[4], bh23[4];
            LDSM4(bh01, bH + k2);
            LDSM4(bh23, bH + nstep + k2);
            #pragma unroll
            for (int mi = 0; mi < 4; mi++) {
                unsigned ah[4];
                LDSM4(ah, aH + mi * mstep + k2);
                mma4(acc[mi][0], ah, bh01[0], bh01[1]);
                mma4(acc[mi][1], ah, bh01[2], bh01[3]);
                mma4(acc[mi][2], ah, bh23[0], bh23[1]);
                mma4(acc[mi][3], ah, bh23[2], bh23[3]);
            }
        }
    }

    #pragma unroll
    for (int ni = 0; ni < 4; ni++) {
        int col = n0 + wn + ni * 8 + tg * 2;
        float b0 = bias[col], b1 = bias[col + 1];
        #pragma unroll
        for (int mi = 0; mi < 4; mi++) {
            int row = m0 + wm + mi * 16 + g;
            float2 o0 = make_float2(acc[mi][ni][0] + b0, acc[mi][ni][1] + b1);
            float2 o1 = make_float2(acc[mi][ni][2] + b0, acc[mi][ni][3] + b1);
            *(float2*)(C + (size_t)row * H3_ + col) = o0;
            *(float2*)(C + (size_t)(row + 8) * H3_ + col) = o1;
        }
    }
}

// ===========================================================================
// Persistent GRU scan v8: DUAL independent chains per block.
// 64 blocks x 512 thr = 2 chains x 256 thr (8 warps = 2m x 4n, FULL k=512,
// no k-split -> register epilogue, no reduction). Chains share read-only W;
// each has its own hs buffer, named barrier, flag set. Flag-based dataflow
// sync across the 16 producer tiles of each batch group.
// ===========================================================================
#define WKS  520
#define HKS  520
#define OFF_HS   99840                  // W: 96*520*2
#define HSB      33280                  // hs per chain: 32*520*2
#define SCAN_SMEM (OFF_HS + 2*HSB)      // 166400

__device__ __forceinline__ void chain_bar(int chain) {
    asm volatile("bar.sync %0, 256;" :: "r"(1 + chain) : "memory");
}

__global__ __launch_bounds__(SNTHR, 1)
void gru_scan_kernel(const float* __restrict__ rnn_state,
                     const float* __restrict__ Whrz,
                     const float* __restrict__ Whn,
                     const float* __restrict__ bhn,
                     const float* __restrict__ gi,
                     float* __restrict__ ys)
{
    extern __shared__ char smraw[];
    __half* Whi = (__half*)smraw;

    const int tid  = threadIdx.x;
    const int chain = tid >> 8;
    const int tc   = tid & 255;
    const int bid  = blockIdx.x;
    const int hti  = bid & 15;
    const int grp  = (bid >> 4) * 2 + chain;   // 0..7
    const int hb   = hti * 32;
    const int b0   = grp * 32;

    const int w    = tc >> 5, lane = tc & 31;
    const int wm   = (w & 1) * 16;
    const int nidx = w >> 1;                   // 0..3
    const int g    = lane >> 2;
    const int tg   = lane & 3;

    // conversion: one row, 64 k per thread
    const int crow = tc & 31;
    const int ck   = (tc >> 5) * 64;

    __half* hs = (__half*)(smraw + OFF_HS + chain * HSB);
    const uint32_t smb = smem_u32(smraw);

    // ldmatrix bases (gate-aligned W strips: row = gate*32 + nidx*8 + r)
    const uint32_t wH01 = smb + ((((lane & 16) ? 32 : 0) + nidx * 8 + (lane & 7)) * WKS
                          + ((lane & 8) ? 8 : 0)) * 2;
    const uint32_t wH2  = smb + ((64 + nidx * 8 + (lane & 7)) * WKS
                          + ((lane & 8) ? 8 : 0)) * 2;
    const uint32_t hA   = smb + OFF_HS + chain * HSB +
                          ((wm + (lane & 15)) * HKS + ((lane & 16) ? 8 : 0)) * 2;

    // ---- one-time: W slice -> fp16 resident [96][WKS] (both chains together)
    for (int i = tid; i < 96 * 128; i += SNTHR) {
        int n = i >> 7, kq = (i & 127) * 4;
        int gate = n >> 5, hcol = hb + (n & 31);
        const float* src;
        int stride;
        if (gate == 0)      { src = Whrz + hcol;      stride = H2_; }
        else if (gate == 1) { src = Whrz + H_ + hcol; stride = H2_; }
        else                { src = Whn + hcol;       stride = H_;  }
        float4 v;
        v.x = src[(size_t)(kq + 0) * stride];
        v.y = src[(size_t)(kq + 1) * stride];
        v.z = src[(size_t)(kq + 2) * stride];
        v.w = src[(size_t)(kq + 3) * stride];
        *(ull*)&Whi[n * WKS + kq] = cvt4h(v);
    }

    // epilogue constants + h_old registers
    const int eh2 = hb + nidx * 8 + tg * 2;
    const float2 bh2 = *(const float2*)(bhn + eh2);
    float2 prev0 = *(const float2*)(rnn_state + (size_t)(b0 + wm + g) * H_ + eh2);
    float2 prev1 = *(const float2*)(rnn_state + (size_t)(b0 + wm + g + 8) * H_ + eh2);
    __syncthreads();

    volatile unsigned* myflag = &g_flag[(grp * 16 + hti) * 32];

    for (int t = 0; t < T_; t++) {
        const float* hin = (t == 0) ? rnn_state : (ys + (size_t)(t - 1) * B_ * H_);

        // independent prefetches (before the poll)
        const float* gp0 = gi + ((size_t)t * B_ + b0 + wm + g) * H3_ + eh2;
        const float* gp1 = gp0 + (size_t)8 * H3_;
        float2 ir0 = __ldcg((const float2*)(gp0));
        float2 iz0 = __ldcg((const float2*)(gp0 + H_));
        float2 in0 = __ldcg((const float2*)(gp0 + 2 * H_));
        float2 ir1 = __ldcg((const float2*)(gp1));
        float2 iz1 = __ldcg((const float2*)(gp1 + H_));
        float2 in1 = __ldcg((const float2*)(gp1 + 2 * H_));
        const float me0 = __ldg(&g_mask[t * B_ + b0 + wm + g]);
        const float me1 = __ldg(&g_mask[t * B_ + b0 + wm + g + 8]);
        const float mc  = __ldg(&g_mask[t * B_ + b0 + crow]);

        // ---- dataflow wait: all 16 producer tiles of step t-1 (this group)
        if (t > 0 && tc < 16) {
            volatile unsigned* f = &g_flag[(grp * 16 + tc) * 32];
            while (*f < (unsigned)t) __nanosleep(32);
            __threadfence();
        }
        chain_bar(chain);

        // ---- convert this chain's h tile [32][512] -> fp16 smem (masked)
        {
            const float* src = hin + (size_t)(b0 + crow) * H_ + ck;
            #pragma unroll
            for (int q = 0; q < 4; q++) {
                float4 f0 = __ldcg((const float4*)(src + q * 16));
                float4 f1 = __ldcg((const float4*)(src + q * 16 + 4));
                float4 f2 = __ldcg((const float4*)(src + q * 16 + 8));
                float4 f3 = __ldcg((const float4*)(src + q * 16 + 12));
                f0.x*=mc; f0.y*=mc; f0.z*=mc; f0.w*=mc;
                f1.x*=mc; f1.y*=mc; f1.z*=mc; f1.w*=mc;
                f2.x*=mc; f2.y*=mc; f2.z*=mc; f2.w*=mc;
                f3.x*=mc; f3.y*=mc; f3.z*=mc; f3.w*=mc;
                ulonglong2 u0, u1;
                u0.x = cvt4h(f0); u0.y = cvt4h(f1);
                u1.x = cvt4h(f2); u1.y = cvt4h(f3);
                *(ulonglong2*)&hs[crow * HKS + ck + q * 16] = u0;
                *(ulonglong2*)&hs[crow * HKS + ck + q * 16 + 8] = u1;
            }
        }
        chain_bar(chain);

        // ---- mma: full k = 512 per warp
        float acc[3][4];
        #pragma unroll
        for (int ni = 0; ni < 3; ni++)
            #pragma unroll
            for (int q = 0; q < 4; q++) acc[ni][q] = 0.0f;

        #pragma unroll
        for (int ks = 0; ks < 32; ks++) {
            const int kw2 = ks * 32;
            unsigned wh01[4], wh2[2], ah[4];
            LDSM4(wh01, wH01 + kw2);
            LDSM2(wh2,  wH2 + kw2);
            LDSM4(ah,   hA + kw2);
            mma4(acc[0], ah, wh01[0], wh01[1]);
            mma4(acc[1], ah, wh01[2], wh01[3]);
            mma4(acc[2], ah, wh2[0], wh2[1]);
        }

        // ---- in-register epilogue (gate-aligned: this thread owns r/z/n)
        #pragma unroll
        for (int mrow = 0; mrow < 2; mrow++) {
            const int b = b0 + wm + g + 8 * mrow;
            const float me = mrow ? me1 : me0;
            const float2 pv = mrow ? prev1 : prev0;
            const float2 ir = mrow ? ir1 : ir0;
            const float2 iz = mrow ? iz1 : iz0;
            const float2 in_ = mrow ? in1 : in0;
            const int q0 = mrow * 2;

            float hm0 = pv.x * me, hm1 = pv.y * me;
            float r0 = 1.0f / (1.0f + __expf(-(ir.x + acc[0][q0])));
            float r1 = 1.0f / (1.0f + __expf(-(ir.y + acc[0][q0 + 1])));
            float z0 = 1.0f / (1.0f + __expf(-(iz.x + acc[1][q0])));
            float z1 = 1.0f / (1.0f + __expf(-(iz.y + acc[1][q0 + 1])));
            float e0 = __expf(2.0f * (in_.x + r0 * (acc[2][q0] + bh2.x)));
            float e1 = __expf(2.0f * (in_.y + r1 * (acc[2][q0 + 1] + bh2.y)));
            float n0 = __fdividef(e0 - 1.0f, e0 + 1.0f);
            float n1 = __fdividef(e1 - 1.0f, e1 + 1.0f);

            float2 out;
            out.x = (1.0f - z0) * n0 + z0 * hm0;
            out.y = (1.0f - z1) * n1 + z1 * hm1;
            *(float2*)(ys + ((size_t)t * B_ + b) * H_ + eh2) = out;
            if (mrow) prev1 = out; else prev0 = out;
        }

        chain_bar(chain);          // all chain STGs issued before release

        if (tc == 0) {
            __threadfence();
            *myflag = t + 1;
        }
    }
}

// ===========================================================================
extern "C" void kernel_launch(void* const* d_in, const int* in_sizes, int n_in,
                              void* d_out, int out_size)
{
    const float* rnn_state = (const float*)d_in[0];
    const float* ins       = (const float*)d_in[1];
    const void*  resets    = d_in[2];
    const float* Wi        = (const float*)d_in[3];
    const float* bi        = (const float*)d_in[4];
    const float* Whrz      = (const float*)d_in[5];
    const float* Whn       = (const float*)d_in[6];
    const float* bhn       = (const float*)d_in[7];

    float* final_h = (float*)d_out;
    float* ys      = (float*)d_out + (size_t)B_ * H_;

    float* gi_ptr = nullptr;
    cudaGetSymbolAddress((void**)&gi_ptr, g_gi);

    cudaFuncSetAttribute(gru_scan_kernel,
                         cudaFuncAttributeMaxDynamicSharedMemorySize, SCAN_SMEM);

    prep_mask_kernel<<<1, 1024>>>(resets);               // launch #3
    conv_ab_kernel<<<2048, 256>>>(ins, Wi);              // launch #4
    gi_gemm_kernel<<<dim3(H3_ / 128, (T_ * B_) / 128), 256>>>(bi, gi_ptr);  // #5
    gru_scan_kernel<<<SNBLK, SNTHR, SCAN_SMEM>>>(rnn_state, Whrz, Whn, bhn,
                                                 gi_ptr, ys);               // #6
    cudaMemcpyAsync(final_h, ys + (size_t)(T_ - 1) * B_ * H_,
                    (size_t)B_ * H_ * sizeof(float),
                    cudaMemcpyDeviceToDevice, 0);
}

// round 13
// speedup vs baseline: 1.6415x; 1.6415x over previous
#include <cuda_runtime.h>
#include <cuda_fp16.h>
#include <math.h>
#include <cstdint>

#define T_  512
#define B_  256
#define D_  512
#define H_  512
#define H2_ (2*H_)
#define H3_ (3*H_)

#define NBLK  128
#define SNTHR 512

typedef unsigned long long ull;

// ===========================================================================
// Global scratch
// ===========================================================================
__device__ float g_gi[(size_t)T_ * B_ * H3_];          // gi = ins @ Wi + bi
__device__ float g_mask[T_ * B_];
__device__ __half g_ah[(size_t)T_ * B_ * D_];          // ins fp16 [m][k]
__device__ __half g_bh[(size_t)H3_ * D_];              // Wi^T fp16 [n][k]
__device__ unsigned g_flag[NBLK * 32];                 // per-tile step flags

// ===========================================================================
// helpers
// ===========================================================================
__device__ __forceinline__ uint32_t smem_u32(const void* p) {
    uint32_t a;
    asm("{ .reg .u64 t; cvta.to.shared.u64 t, %1; cvt.u32.u64 %0, t; }"
        : "=r"(a) : "l"(p));
    return a;
}

#define LDSM4(R, A) \
    asm volatile("ldmatrix.sync.aligned.m8n8.x4.shared.b16 {%0,%1,%2,%3}, [%4];" \
        : "=r"((R)[0]), "=r"((R)[1]), "=r"((R)[2]), "=r"((R)[3]) : "r"(A))
#define LDSM2(R, A) \
    asm volatile("ldmatrix.sync.aligned.m8n8.x2.shared.b16 {%0,%1}, [%2];" \
        : "=r"((R)[0]), "=r"((R)[1]) : "r"(A))

__device__ __forceinline__ void mma4(float* c, const unsigned* a,
                                     unsigned b0, unsigned b1) {
    asm volatile(
        "mma.sync.aligned.m16n8k16.row.col.f32.f16.f16.f32 "
        "{%0,%1,%2,%3}, {%4,%5,%6,%7}, {%8,%9}, {%0,%1,%2,%3};"
        : "+f"(c[0]), "+f"(c[1]), "+f"(c[2]), "+f"(c[3])
        : "r"(a[0]), "r"(a[1]), "r"(a[2]), "r"(a[3]), "r"(b0), "r"(b1));
}

__device__ __forceinline__ ull cvt4h(float4 v) {
    __half2 a = __floats2half2_rn(v.x, v.y);
    __half2 b = __floats2half2_rn(v.z, v.w);
    ull r;
    asm("mov.b64 %0, {%1, %2};" : "=l"(r)
        : "r"(*(unsigned*)&a), "r"(*(unsigned*)&b));
    return r;
}

// ===========================================================================
// Reset-mask prep + flag reset (every call — graph replay safe)
// ===========================================================================
__global__ void prep_mask_kernel(const void* __restrict__ resets)
{
    const int N = T_ * B_;
    for (int i = threadIdx.x; i < NBLK * 32; i += blockDim.x)
        g_flag[i] = 0;
    const unsigned char* b8 = (const unsigned char*)resets;
    int found = 0;
    for (int i = threadIdx.x; i < N; i += blockDim.x)
        if ((i & 3) && b8[i] == 1) found = 1;
    int is_byte = __syncthreads_or(found);
    if (is_byte) {
        for (int i = threadIdx.x; i < N; i += blockDim.x)
            g_mask[i] = b8[i] ? 0.0f : 1.0f;
    } else {
        const unsigned int* w32 = (const unsigned int*)resets;
        for (int i = threadIdx.x; i < N; i += blockDim.x)
            g_mask[i] = w32[i] ? 0.0f : 1.0f;
    }
}

// ===========================================================================
// fp16 conversion for A (ins) and B (Wi^T)
// ===========================================================================
__global__ void conv_ab_kernel(const float* __restrict__ ins,
                               const float* __restrict__ Wi)
{
    const size_t totalA = (size_t)T_ * B_ * D_ / 8;
    const size_t totalB = (size_t)H3_ * (D_ / 8);
    const size_t total = totalA + totalB;
    for (size_t i = (size_t)blockIdx.x * blockDim.x + threadIdx.x;
         i < total; i += (size_t)gridDim.x * blockDim.x) {
        if (i < totalA) {
            size_t base = i * 8;
            float4 a = *(const float4*)(ins + base);
            float4 b = *(const float4*)(ins + base + 4);
            *(ull*)&g_ah[base] = cvt4h(a);
            *(ull*)&g_ah[base + 4] = cvt4h(b);
        } else {
            size_t j = i - totalA;
            int n = (int)(j % H3_);
            int k8 = (int)(j / H3_) * 8;
            float4 a, b;
            a.x = Wi[(size_t)(k8+0)*H3_ + n]; a.y = Wi[(size_t)(k8+1)*H3_ + n];
            a.z = Wi[(size_t)(k8+2)*H3_ + n]; a.w = Wi[(size_t)(k8+3)*H3_ + n];
            b.x = Wi[(size_t)(k8+4)*H3_ + n]; b.y = Wi[(size_t)(k8+5)*H3_ + n];
            b.z = Wi[(size_t)(k8+6)*H3_ + n]; b.w = Wi[(size_t)(k8+7)*H3_ + n];
            size_t o = (size_t)n * D_ + k8;
            *(ull*)&g_bh[o] = cvt4h(a);
            *(ull*)&g_bh[o + 4] = cvt4h(b);
        }
    }
}

// ===========================================================================
// gi GEMM (unchanged — proven)
// ===========================================================================
#define SAK 40

__global__ __launch_bounds__(256)
void gi_gemm_kernel(const float* __restrict__ bias, float* __restrict__ C)
{
    __shared__ __half sAh[128 * SAK];
    __shared__ __half sBh[128 * SAK];

    const int tid = threadIdx.x;
    const int n0  = blockIdx.x * 128;
    const int m0  = blockIdx.y * 128;
    const int wid = tid >> 5, lane = tid & 31;
    const int wm = (wid & 1) * 64;
    const int wn = (wid >> 1) * 32;
    const int g  = lane >> 2;
    const int tg = lane & 3;

    const int sr = tid >> 1, sk = (tid & 1) * 16;
    const __half* pAh = g_ah + (size_t)(m0 + sr) * D_ + sk;
    const __half* pBh = g_bh + (size_t)(n0 + sr) * D_ + sk;

    const uint32_t aH = smem_u32(sAh) + (((wm + (lane & 15)) * SAK) +
                        ((lane & 16) ? 8 : 0)) * 2;
    const uint32_t bH = smem_u32(sBh) + (((wn + (lane & 7) +
                        ((lane & 16) ? 8 : 0)) * SAK) +
                        ((lane & 8) ? 8 : 0)) * 2;
    const int mstep = 16 * SAK * 2;
    const int nstep = 16 * SAK * 2;

    float acc[4][4][4];
    #pragma unroll
    for (int i = 0; i < 4; i++)
        #pragma unroll
        for (int j = 0; j < 4; j++)
            #pragma unroll
            for (int q = 0; q < 4; q++) acc[i][j][q] = 0.0f;

    uint4 rah0, rah1, rbh0, rbh1;
    rah0 = *(const uint4*)(pAh);     rah1 = *(const uint4*)(pAh + 8);
    rbh0 = *(const uint4*)(pBh);     rbh1 = *(const uint4*)(pBh + 8);

    for (int kc = 0; kc < D_ / 32; kc++) {
        __syncthreads();
        *(uint4*)&sAh[sr * SAK + sk] = rah0;  *(uint4*)&sAh[sr * SAK + sk + 8] = rah1;
        *(uint4*)&sBh[sr * SAK + sk] = rbh0;  *(uint4*)&sBh[sr * SAK + sk + 8] = rbh1;
        __syncthreads();

        if (kc + 1 < D_ / 32) {
            int k0 = (kc + 1) * 32;
            rah0 = *(const uint4*)(pAh + k0);  rah1 = *(const uint4*)(pAh + k0 + 8);
            rbh0 = *(const uint4*)(pBh + k0);  rbh1 = *(const uint4*)(pBh + k0 + 8);
        }

        #pragma unroll
        for (int ks = 0; ks < 2; ks++) {
            const int k2 = ks * 32;
            unsigned bh01[4], bh23[4];
            LDSM4(bh01, bH + k2);
            LDSM4(bh23, bH + nstep + k2);
            #pragma unroll
            for (int mi = 0; mi < 4; mi++) {
                unsigned ah[4];
                LDSM4(ah, aH + mi * mstep + k2);
                mma4(acc[mi][0], ah, bh01[0], bh01[1]);
                mma4(acc[mi][1], ah, bh01[2], bh01[3]);
                mma4(acc[mi][2], ah, bh23[0], bh23[1]);
                mma4(acc[mi][3], ah, bh23[2], bh23[3]);
            }
        }
    }

    #pragma unroll
    for (int ni = 0; ni < 4; ni++) {
        int col = n0 + wn + ni * 8 + tg * 2;
        float b0 = bias[col], b1 = bias[col + 1];
        #pragma unroll
        for (int mi = 0; mi < 4; mi++) {
            int row = m0 + wm + mi * 16 + g;
            float2 o0 = make_float2(acc[mi][ni][0] + b0, acc[mi][ni][1] + b1);
            float2 o1 = make_float2(acc[mi][ni][2] + b0, acc[mi][ni][3] + b1);
            *(float2*)(C + (size_t)row * H3_ + col) = o0;
            *(float2*)(C + (size_t)(row + 8) * H3_ + col) = o1;
        }
    }
}

// ===========================================================================
// Persistent GRU scan v9 = R10 skeleton (128 blk, 2-chunk pipeline, k-split)
//   + flag dataflow sync (no global barrier)
//   + gate-aligned n-strips with in-register epilogue (h_old in registers)
// 512 thr = 16 warps = 2m x 4n(8-col gate-aligned strips) x 2 k-halves.
// ===========================================================================
#define WKS  520
#define HKS  136                         // h chunk row stride (elems)
#define HSBUF 8704                       // bytes per buffer: 32*136*2
#define OFF_HS   99840                   // W: 96*520*2
#define OFF_GRED (OFF_HS + 4*HSBUF)      // 134656
#define SCAN_SMEM (OFF_GRED + 12288)     // 146944 bytes

__global__ __launch_bounds__(SNTHR, 1)
void gru_scan_kernel(const float* __restrict__ rnn_state,
                     const float* __restrict__ Whrz,
                     const float* __restrict__ Whn,
                     const float* __restrict__ bhn,
                     const float* __restrict__ gi,
                     float* __restrict__ ys)
{
    extern __shared__ char smraw[];
    __half* Whi  = (__half*)smraw;
    float*  gred = (float*)(smraw + OFF_GRED);

    const int tid = threadIdx.x;
    const int bid = blockIdx.x;
    const int hti = bid & 15, bti = bid >> 4;
    const int hb  = hti * 32;
    const int b0  = bti * 32;

    const int wid = tid >> 5, lane = tid & 31;
    const int kh  = wid >> 3;                // k half
    const int w7  = wid & 7;
    const int wm  = (w7 & 1) * 16;           // m offset
    const int nidx = w7 >> 1;                // h strip (8 cols)
    const int g   = lane >> 2;
    const int tg  = lane & 3;

    // conversion slot: row = tid>>4 (0..31), k8 = (tid&15)*8
    const int crow = tid >> 4;
    const int ck8  = (tid & 15) * 8;

    const uint32_t smb = smem_u32(smraw);

    // ldmatrix bases: gate-aligned W strips (row = gate*32 + nidx*8 + r)
    const uint32_t wH01 = smb + ((((lane & 16) ? 32 : 0) + nidx * 8 + (lane & 7)) * WKS
                          + ((lane & 8) ? 8 : 0)) * 2;
    const uint32_t wH2  = smb + ((64 + nidx * 8 + (lane & 7)) * WKS
                          + ((lane & 8) ? 8 : 0)) * 2;
    const uint32_t hLane = (((wm + (lane & 15)) * HKS) + ((lane & 16) ? 8 : 0)) * 2;

    // ---- one-time: W slice -> fp16 resident [96][WKS]
    for (int i = tid; i < 96 * 128; i += SNTHR) {
        int n = i >> 7, kq = (i & 127) * 4;
        int gate = n >> 5, hcol = hb + (n & 31);
        const float* src;
        int stride;
        if (gate == 0)      { src = Whrz + hcol;      stride = H2_; }
        else if (gate == 1) { src = Whrz + H_ + hcol; stride = H2_; }
        else                { src = Whn + hcol;       stride = H_;  }
        float4 v;
        v.x = src[(size_t)(kq + 0) * stride];
        v.y = src[(size_t)(kq + 1) * stride];
        v.z = src[(size_t)(kq + 2) * stride];
        v.w = src[(size_t)(kq + 3) * stride];
        *(ull*)&Whi[n * WKS + kq] = cvt4h(v);
    }

    // epilogue constants + h_old registers (kh0 threads own the outputs)
    const int eh2 = hb + nidx * 8 + tg * 2;
    const float2 bh2 = *(const float2*)(bhn + eh2);
    float2 prev0 = *(const float2*)(rnn_state + (size_t)(b0 + wm + g) * H_ + eh2);
    float2 prev1 = *(const float2*)(rnn_state + (size_t)(b0 + wm + g + 8) * H_ + eh2);
    __syncthreads();

    volatile unsigned* myflag = &g_flag[(bti * 16 + hti) * 32];

    for (int t = 0; t < T_; t++) {
        const float* hin = (t == 0) ? rnn_state : (ys + (size_t)(t - 1) * B_ * H_);

        // independent prefetches (safe before the flag wait)
        float2 ir0, iz0, in0, ir1, iz1, in1;
        float me0 = 0.f, me1 = 0.f;
        if (kh == 0) {
            const float* gp0 = gi + ((size_t)t * B_ + b0 + wm + g) * H3_ + eh2;
            const float* gp1 = gp0 + (size_t)8 * H3_;
            ir0 = __ldcg((const float2*)(gp0));
            iz0 = __ldcg((const float2*)(gp0 + H_));
            in0 = __ldcg((const float2*)(gp0 + 2 * H_));
            ir1 = __ldcg((const float2*)(gp1));
            iz1 = __ldcg((const float2*)(gp1 + H_));
            in1 = __ldcg((const float2*)(gp1 + 2 * H_));
            me0 = __ldg(&g_mask[t * B_ + b0 + wm + g]);
            me1 = __ldg(&g_mask[t * B_ + b0 + wm + g + 8]);
        }
        const float mc = __ldg(&g_mask[t * B_ + b0 + crow]);

        // ---- dataflow wait: all 16 producer tiles of step t-1 (this group)
        if (t > 0 && tid < 16) {
            volatile unsigned* f = &g_flag[(bti * 16 + tid) * 32];
            while (*f < (unsigned)t) __nanosleep(32);
            __threadfence();
        }
        __syncthreads();

        // h row pointers: half A k[0,256), half B k[256,512)
        const float* hrA = hin + (size_t)(b0 + crow) * H_ + ck8;
        const float* hrB = hrA + 256;

        float4 vA0 = __ldcg((const float4*)(hrA));
        float4 vA1 = __ldcg((const float4*)(hrA + 4));
        float4 vB0 = __ldcg((const float4*)(hrB));
        float4 vB1 = __ldcg((const float4*)(hrB + 4));

        float acc[3][4];
        #pragma unroll
        for (int ni = 0; ni < 3; ni++)
            #pragma unroll
            for (int q = 0; q < 4; q++) acc[ni][q] = 0.0f;

        // ---- chunk 0 convert (both halves)
        {
            __half* bufA = (__half*)(smraw + OFF_HS);            // half0 c0
            __half* bufB = (__half*)(smraw + OFF_HS + 2*HSBUF);  // half1 c0
            *(ull*)&bufA[crow * HKS + ck8] =
                cvt4h(make_float4(vA0.x*mc, vA0.y*mc, vA0.z*mc, vA0.w*mc));
            *(ull*)&bufA[crow * HKS + ck8 + 4] =
                cvt4h(make_float4(vA1.x*mc, vA1.y*mc, vA1.z*mc, vA1.w*mc));
            *(ull*)&bufB[crow * HKS + ck8] =
                cvt4h(make_float4(vB0.x*mc, vB0.y*mc, vB0.z*mc, vB0.w*mc));
            *(ull*)&bufB[crow * HKS + ck8 + 4] =
                cvt4h(make_float4(vB1.x*mc, vB1.y*mc, vB1.z*mc, vB1.w*mc));
        }
        __syncthreads();

        // prefetch chunk 1
        vA0 = __ldcg((const float4*)(hrA + 128));
        vA1 = __ldcg((const float4*)(hrA + 132));
        vB0 = __ldcg((const float4*)(hrB + 128));
        vB1 = __ldcg((const float4*)(hrB + 132));

        // ---- mma chunk 0
        {
            const uint32_t hA = smb + OFF_HS + (kh * 2) * HSBUF + hLane;
            #pragma unroll
            for (int ks = 0; ks < 8; ks++) {
                const int kw2 = (kh * 256 + ks * 16) * 2;
                const int kl2 = ks * 32;
                unsigned wh01[4], wh2[2], ah[4];
                LDSM4(wh01, wH01 + kw2);
                LDSM2(wh2,  wH2 + kw2);
                LDSM4(ah,   hA + kl2);
                mma4(acc[0], ah, wh01[0], wh01[1]);
                mma4(acc[1], ah, wh01[2], wh01[3]);
                mma4(acc[2], ah, wh2[0], wh2[1]);
            }
        }

        // ---- chunk 1 convert
        {
            __half* bufA = (__half*)(smraw + OFF_HS + 1*HSBUF);
            __half* bufB = (__half*)(smraw + OFF_HS + 3*HSBUF);
            *(ull*)&bufA[crow * HKS + ck8] =
                cvt4h(make_float4(vA0.x*mc, vA0.y*mc, vA0.z*mc, vA0.w*mc));
            *(ull*)&bufA[crow * HKS + ck8 + 4] =
                cvt4h(make_float4(vA1.x*mc, vA1.y*mc, vA1.z*mc, vA1.w*mc));
            *(ull*)&bufB[crow * HKS + ck8] =
                cvt4h(make_float4(vB0.x*mc, vB0.y*mc, vB0.z*mc, vB0.w*mc));
            *(ull*)&bufB[crow * HKS + ck8 + 4] =
                cvt4h(make_float4(vB1.x*mc, vB1.y*mc, vB1.z*mc, vB1.w*mc));
        }
        __syncthreads();

        // ---- mma chunk 1
        {
            const uint32_t hA = smb + OFF_HS + (kh * 2 + 1) * HSBUF + hLane;
            #pragma unroll
            for (int ks = 0; ks < 8; ks++) {
                const int kw2 = (kh * 256 + 128 + ks * 16) * 2;
                const int kl2 = ks * 32;
                unsigned wh01[4], wh2[2], ah[4];
                LDSM4(wh01, wH01 + kw2);
                LDSM2(wh2,  wH2 + kw2);
                LDSM4(ah,   hA + kl2);
                mma4(acc[0], ah, wh01[0], wh01[1]);
                mma4(acc[1], ah, wh01[2], wh01[3]);
                mma4(acc[2], ah, wh2[0], wh2[1]);
            }
        }
        __syncthreads();

        // ---- kh1 partials -> gred; kh0 adds + in-register gates
        float* gp = &gred[(w7 * 32 + lane) * 12];
        if (kh == 1) {
            #pragma unroll
            for (int ni = 0; ni < 3; ni++)
                #pragma unroll
                for (int q = 0; q < 4; q++) gp[ni * 4 + q] = acc[ni][q];
        }
        __syncthreads();

        if (kh == 0) {
            #pragma unroll
            for (int ni = 0; ni < 3; ni++)
                #pragma unroll
                for (int q = 0; q < 4; q++) acc[ni][q] += gp[ni * 4 + q];

            #pragma unroll
            for (int mrow = 0; mrow < 2; mrow++) {
                const int b = b0 + wm + g + 8 * mrow;
                const float me = mrow ? me1 : me0;
                const float2 pv = mrow ? prev1 : prev0;
                const float2 ir = mrow ? ir1 : ir0;
                const float2 iz = mrow ? iz1 : iz0;
                const float2 in_ = mrow ? in1 : in0;
                const int q0 = mrow * 2;

                float hm0 = pv.x * me, hm1 = pv.y * me;
                float r0 = 1.0f / (1.0f + __expf(-(ir.x + acc[0][q0])));
                float r1 = 1.0f / (1.0f + __expf(-(ir.y + acc[0][q0 + 1])));
                float z0 = 1.0f / (1.0f + __expf(-(iz.x + acc[1][q0])));
                float z1 = 1.0f / (1.0f + __expf(-(iz.y + acc[1][q0 + 1])));
                float e0 = __expf(2.0f * (in_.x + r0 * (acc[2][q0] + bh2.x)));
                float e1 = __expf(2.0f * (in_.y + r1 * (acc[2][q0 + 1] + bh2.y)));
                float n0 = __fdividef(e0 - 1.0f, e0 + 1.0f);
                float n1 = __fdividef(e1 - 1.0f, e1 + 1.0f);

                float2 out;
                out.x = (1.0f - z0) * n0 + z0 * hm0;
                out.y = (1.0f - z1) * n1 + z1 * hm1;
                *(float2*)(ys + ((size_t)t * B_ + b) * H_ + eh2) = out;
                if (mrow) prev1 = out; else prev0 = out;
            }
        }
        __syncthreads();

        // ---- release: this tile of step t is visible
        if (tid == 0) {
            __threadfence();
            *myflag = t + 1;
        }
    }
}

// ===========================================================================
extern "C" void kernel_launch(void* const* d_in, const int* in_sizes, int n_in,
                              void* d_out, int out_size)
{
    const float* rnn_state = (const float*)d_in[0];
    const float* ins       = (const float*)d_in[1];
    const void*  resets    = d_in[2];
    const float* Wi        = (const float*)d_in[3];
    const float* bi        = (const float*)d_in[4];
    const float* Whrz      = (const float*)d_in[5];
    const float* Whn       = (const float*)d_in[6];
    const float* bhn       = (const float*)d_in[7];

    float* final_h = (float*)d_out;
    float* ys      = (float*)d_out + (size_t)B_ * H_;

    float* gi_ptr = nullptr;
    cudaGetSymbolAddress((void**)&gi_ptr, g_gi);

    cudaFuncSetAttribute(gru_scan_kernel,
                         cudaFuncAttributeMaxDynamicSharedMemorySize, SCAN_SMEM);

    prep_mask_kernel<<<1, 1024>>>(resets);               // launch #3
    conv_ab_kernel<<<2048, 256>>>(ins, Wi);              // launch #4
    gi_gemm_kernel<<<dim3(H3_ / 128, (T_ * B_) / 128), 256>>>(bi, gi_ptr);  // #5
    gru_scan_kernel<<<NBLK, SNTHR, SCAN_SMEM>>>(rnn_state, Whrz, Whn, bhn,
                                                gi_ptr, ys);                // #6
    cudaMemcpyAsync(final_h, ys + (size_t)(T_ - 1) * B_ * H_,
                    (size_t)B_ * H_ * sizeof(float),
                    cudaMemcpyDeviceToDevice, 0);
}

// round 15
// speedup vs baseline: 1.6443x; 1.0017x over previous
#include <cuda_runtime.h>
#include <cuda_fp16.h>
#include <math.h>
#include <cstdint>

#define T_  512
#define B_  256
#define D_  512
#define H_  512
#define H2_ (2*H_)
#define H3_ (3*H_)

#define NBLK  128
#define SNTHR 512

typedef unsigned long long ull;

// ===========================================================================
// Global scratch
// ===========================================================================
__device__ float g_gi[(size_t)T_ * B_ * H3_];          // gi = ins @ Wi + bi
__device__ float g_mask[T_ * B_];
__device__ __half g_ah[(size_t)T_ * B_ * D_];          // ins fp16 [m][k]
__device__ __half g_bh[(size_t)H3_ * D_];              // Wi^T fp16 [n][k]
__device__ __half g_hs[(size_t)T_ * B_ * H_];          // h states fp16 (unmasked)
__device__ unsigned g_flag[NBLK * 32];                 // per-tile step flags

// ===========================================================================
// helpers
// ===========================================================================
__device__ __forceinline__ uint32_t smem_u32(const void* p) {
    uint32_t a;
    asm("{ .reg .u64 t; cvta.to.shared.u64 t, %1; cvt.u32.u64 %0, t; }"
        : "=r"(a) : "l"(p));
    return a;
}

#define LDSM4(R, A) \
    asm volatile("ldmatrix.sync.aligned.m8n8.x4.shared.b16 {%0,%1,%2,%3}, [%4];" \
        : "=r"((R)[0]), "=r"((R)[1]), "=r"((R)[2]), "=r"((R)[3]) : "r"(A))
#define LDSM2(R, A) \
    asm volatile("ldmatrix.sync.aligned.m8n8.x2.shared.b16 {%0,%1}, [%2];" \
        : "=r"((R)[0]), "=r"((R)[1]) : "r"(A))

__device__ __forceinline__ void mma4(float* c, const unsigned* a,
                                     unsigned b0, unsigned b1) {
    asm volatile(
        "mma.sync.aligned.m16n8k16.row.col.f32.f16.f16.f32 "
        "{%0,%1,%2,%3}, {%4,%5,%6,%7}, {%8,%9}, {%0,%1,%2,%3};"
        : "+f"(c[0]), "+f"(c[1]), "+f"(c[2]), "+f"(c[3])
        : "r"(a[0]), "r"(a[1]), "r"(a[2]), "r"(a[3]), "r"(b0), "r"(b1));
}

__device__ __forceinline__ ull cvt4h(float4 v) {
    __half2 a = __floats2half2_rn(v.x, v.y);
    __half2 b = __floats2half2_rn(v.z, v.w);
    ull r;
    asm("mov.b64 %0, {%1, %2};" : "=l"(r)
        : "r"(*(unsigned*)&a), "r"(*(unsigned*)&b));
    return r;
}

#define CP_ASYNC16(smem, gptr) \
    asm volatile("cp.async.cg.shared.global [%0], [%1], 16;" \
                 :: "r"(smem), "l"(gptr) : "memory")
#define CP_COMMIT() asm volatile("cp.async.commit_group;" ::: "memory")
#define CP_WAIT0()  asm volatile("cp.async.wait_group 0;" ::: "memory")

// ===========================================================================
// Reset-mask prep + flag reset (every call — graph replay safe)
// ===========================================================================
__global__ void prep_mask_kernel(const void* __restrict__ resets)
{
    const int N = T_ * B_;
    for (int i = threadIdx.x; i < NBLK * 32; i += blockDim.x)
        g_flag[i] = 0;
    const unsigned char* b8 = (const unsigned char*)resets;
    int found = 0;
    for (int i = threadIdx.x; i < N; i += blockDim.x)
        if ((i & 3) && b8[i] == 1) found = 1;
    int is_byte = __syncthreads_or(found);
    if (is_byte) {
        for (int i = threadIdx.x; i < N; i += blockDim.x)
            g_mask[i] = b8[i] ? 0.0f : 1.0f;
    } else {
        const unsigned int* w32 = (const unsigned int*)resets;
        for (int i = threadIdx.x; i < N; i += blockDim.x)
            g_mask[i] = w32[i] ? 0.0f : 1.0f;
    }
}

// ===========================================================================
// fp16 conversion for A (ins) and B (Wi^T)
// ===========================================================================
__global__ void conv_ab_kernel(const float* __restrict__ ins,
                               const float* __restrict__ Wi)
{
    const size_t totalA = (size_t)T_ * B_ * D_ / 8;
    const size_t totalB = (size_t)H3_ * (D_ / 8);
    const size_t total = totalA + totalB;
    for (size_t i = (size_t)blockIdx.x * blockDim.x + threadIdx.x;
         i < total; i += (size_t)gridDim.x * blockDim.x) {
        if (i < totalA) {
            size_t base = i * 8;
            float4 a = *(const float4*)(ins + base);
            float4 b = *(const float4*)(ins + base + 4);
            *(ull*)&g_ah[base] = cvt4h(a);
            *(ull*)&g_ah[base + 4] = cvt4h(b);
        } else {
            size_t j = i - totalA;
            int n = (int)(j % H3_);
            int k8 = (int)(j / H3_) * 8;
            float4 a, b;
            a.x = Wi[(size_t)(k8+0)*H3_ + n]; a.y = Wi[(size_t)(k8+1)*H3_ + n];
            a.z = Wi[(size_t)(k8+2)*H3_ + n]; a.w = Wi[(size_t)(k8+3)*H3_ + n];
            b.x = Wi[(size_t)(k8+4)*H3_ + n]; b.y = Wi[(size_t)(k8+5)*H3_ + n];
            b.z = Wi[(size_t)(k8+6)*H3_ + n]; b.w = Wi[(size_t)(k8+7)*H3_ + n];
            size_t o = (size_t)n * D_ + k8;
            *(ull*)&g_bh[o] = cvt4h(a);
            *(ull*)&g_bh[o + 4] = cvt4h(b);
        }
    }
}

// ===========================================================================
// gi GEMM (unchanged — proven)
// ===========================================================================
#define SAK 40

__global__ __launch_bounds__(256)
void gi_gemm_kernel(const float* __restrict__ bias, float* __restrict__ C)
{
    __shared__ __half sAh[128 * SAK];
    __shared__ __half sBh[128 * SAK];

    const int tid = threadIdx.x;
    const int n0  = blockIdx.x * 128;
    const int m0  = blockIdx.y * 128;
    const int wid = tid >> 5, lane = tid & 31;
    const int wm = (wid & 1) * 64;
    const int wn = (wid >> 1) * 32;
    const int g  = lane >> 2;
    const int tg = lane & 3;

    const int sr = tid >> 1, sk = (tid & 1) * 16;
    const __half* pAh = g_ah + (size_t)(m0 + sr) * D_ + sk;
    const __half* pBh = g_bh + (size_t)(n0 + sr) * D_ + sk;

    const uint32_t aH = smem_u32(sAh) + (((wm + (lane & 15)) * SAK) +
                        ((lane & 16) ? 8 : 0)) * 2;
    const uint32_t bH = smem_u32(sBh) + (((wn + (lane & 7) +
                        ((lane & 16) ? 8 : 0)) * SAK) +
                        ((lane & 8) ? 8 : 0)) * 2;
    const int mstep = 16 * SAK * 2;
    const int nstep = 16 * SAK * 2;

    float acc[4][4][4];
    #pragma unroll
    for (int i = 0; i < 4; i++)
        #pragma unroll
        for (int j = 0; j < 4; j++)
            #pragma unroll
            for (int q = 0; q < 4; q++) acc[i][j][q] = 0.0f;

    uint4 rah0, rah1, rbh0, rbh1;
    rah0 = *(const uint4*)(pAh);     rah1 = *(const uint4*)(pAh + 8);
    rbh0 = *(const uint4*)(pBh);     rbh1 = *(const uint4*)(pBh + 8);

    for (int kc = 0; kc < D_ / 32; kc++) {
        __syncthreads();
        *(uint4*)&sAh[sr * SAK + sk] = rah0;  *(uint4*)&sAh[sr * SAK + sk + 8] = rah1;
        *(uint4*)&sBh[sr * SAK + sk] = rbh0;  *(uint4*)&sBh[sr * SAK + sk + 8] = rbh1;
        __syncthreads();

        if (kc + 1 < D_ / 32) {
            int k0 = (kc + 1) * 32;
            rah0 = *(const uint4*)(pAh + k0);  rah1 = *(const uint4*)(pAh + k0 + 8);
            rbh0 = *(const uint4*)(pBh + k0);  rbh1 = *(const uint4*)(pBh + k0 + 8);
        }

        #pragma unroll
        for (int ks = 0; ks < 2; ks++) {
            const int k2 = ks * 32;
            unsigned bh01[4], bh23[4];
            LDSM4(bh01, bH + k2);
            LDSM4(bh23, bH + nstep + k2);
            #pragma unroll
            for (int mi = 0; mi < 4; mi++) {
                unsigned ah[4];
                LDSM4(ah, aH + mi * mstep + k2);
                mma4(acc[mi][0], ah, bh01[0], bh01[1]);
                mma4(acc[mi][1], ah, bh01[2], bh01[3]);
                mma4(acc[mi][2], ah, bh23[0], bh23[1]);
                mma4(acc[mi][3], ah, bh23[2], bh23[3]);
            }
        }
    }

    #pragma unroll
    for (int ni = 0; ni < 4; ni++) {
        int col = n0 + wn + ni * 8 + tg * 2;
        float b0 = bias[col], b1 = bias[col + 1];
        #pragma unroll
        for (int mi = 0; mi < 4; mi++) {
            int row = m0 + wm + mi * 16 + g;
            float2 o0 = make_float2(acc[mi][ni][0] + b0, acc[mi][ni][1] + b1);
            float2 o1 = make_float2(acc[mi][ni][2] + b0, acc[mi][ni][3] + b1);
            *(float2*)(C + (size_t)row * H3_ + col) = o0;
            *(float2*)(C + (size_t)(row + 8) * H3_ + col) = o1;
        }
    }
}

// ===========================================================================
// Persistent GRU scan v10b: fp16 h-state scratch + cp.async direct g->s.
// FIX vs R14: hs row stride = 520 halves (holds full k=512; 1040B rows are
// 16B-aligned and ldmatrix-conflict-free, same pattern as the W array).
// Mask factored out of the GEMM ((m*h)@W = m*(h@W)), applied in epilogue.
// ===========================================================================
#define WKS  520
#define HKS2 520                          // hs row stride (halves) = 1040 B
#define OFF_HS   99840                    // W: 96*520*2
#define OFF_GRED (OFF_HS + 32*HKS2*2)     // 99840 + 33280 = 133120
#define SCAN_SMEM (OFF_GRED + 12288)      // 145408 bytes

__global__ __launch_bounds__(SNTHR, 1)
void gru_scan_kernel(const float* __restrict__ rnn_state,
                     const float* __restrict__ Whrz,
                     const float* __restrict__ Whn,
                     const float* __restrict__ bhn,
                     const float* __restrict__ gi,
                     float* __restrict__ ys)
{
    extern __shared__ char smraw[];
    __half* Whi  = (__half*)smraw;
    __half* hs   = (__half*)(smraw + OFF_HS);
    float*  gred = (float*)(smraw + OFF_GRED);

    const int tid = threadIdx.x;
    const int bid = blockIdx.x;
    const int hti = bid & 15, bti = bid >> 4;
    const int hb  = hti * 32;
    const int b0  = bti * 32;

    const int wid = tid >> 5, lane = tid & 31;
    const int kh  = wid >> 3;                // k half
    const int w7  = wid & 7;
    const int wm  = (w7 & 1) * 16;           // m offset
    const int nidx = w7 >> 1;                // h strip (8 cols)
    const int g   = lane >> 2;
    const int tg  = lane & 3;

    // cp.async slot: row = tid>>4 (0..31), 32 halves at col (tid&15)*32
    const int crow = tid >> 4;
    const int ccol = (tid & 15) * 32;

    const uint32_t smb = smem_u32(smraw);

    // ldmatrix bases: gate-aligned W strips (row = gate*32 + nidx*8 + r)
    const uint32_t wH01 = smb + ((((lane & 16) ? 32 : 0) + nidx * 8 + (lane & 7)) * WKS
                          + ((lane & 8) ? 8 : 0)) * 2;
    const uint32_t wH2  = smb + ((64 + nidx * 8 + (lane & 7)) * WKS
                          + ((lane & 8) ? 8 : 0)) * 2;
    const uint32_t hA   = smb + OFF_HS +
                          (((wm + (lane & 15)) * HKS2) + ((lane & 16) ? 8 : 0)) * 2;

    // ---- one-time: W slice -> fp16 resident [96][WKS]
    for (int i = tid; i < 96 * 128; i += SNTHR) {
        int n = i >> 7, kq = (i & 127) * 4;
        int gate = n >> 5, hcol = hb + (n & 31);
        const float* src;
        int stride;
        if (gate == 0)      { src = Whrz + hcol;      stride = H2_; }
        else if (gate == 1) { src = Whrz + H_ + hcol; stride = H2_; }
        else                { src = Whn + hcol;       stride = H_;  }
        float4 v;
        v.x = src[(size_t)(kq + 0) * stride];
        v.y = src[(size_t)(kq + 1) * stride];
        v.z = src[(size_t)(kq + 2) * stride];
        v.w = src[(size_t)(kq + 3) * stride];
        *(ull*)&Whi[n * WKS + kq] = cvt4h(v);
    }

    // epilogue constants + h_old registers (kh0 threads own the outputs)
    const int eh2 = hb + nidx * 8 + tg * 2;
    const float2 bh2 = *(const float2*)(bhn + eh2);
    float2 prev0 = *(const float2*)(rnn_state + (size_t)(b0 + wm + g) * H_ + eh2);
    float2 prev1 = *(const float2*)(rnn_state + (size_t)(b0 + wm + g + 8) * H_ + eh2);
    __syncthreads();

    volatile unsigned* myflag = &g_flag[(bti * 16 + hti) * 32];

    for (int t = 0; t < T_; t++) {
        // independent prefetches (safe before the flag wait)
        float2 ir0, iz0, in0, ir1, iz1, in1;
        float me0 = 0.f, me1 = 0.f;
        if (kh == 0) {
            const float* gp0 = gi + ((size_t)t * B_ + b0 + wm + g) * H3_ + eh2;
            const float* gp1 = gp0 + (size_t)8 * H3_;
            ir0 = __ldcg((const float2*)(gp0));
            iz0 = __ldcg((const float2*)(gp0 + H_));
            in0 = __ldcg((const float2*)(gp0 + 2 * H_));
            ir1 = __ldcg((const float2*)(gp1));
            iz1 = __ldcg((const float2*)(gp1 + H_));
            in1 = __ldcg((const float2*)(gp1 + 2 * H_));
            me0 = __ldg(&g_mask[t * B_ + b0 + wm + g]);
            me1 = __ldg(&g_mask[t * B_ + b0 + wm + g + 8]);
        }

        // ---- dataflow wait: all 16 producer tiles of step t-1 (this group)
        if (t > 0 && tid < 16) {
            volatile unsigned* f = &g_flag[(bti * 16 + tid) * 32];
            while (*f < (unsigned)t) __nanosleep(32);
            __threadfence();
        }
        __syncthreads();

        // ---- load h tile (unmasked) into smem
        if (t == 0) {
            // fp32 rnn_state -> cvt (one-off)
            const float* src = rnn_state + (size_t)(b0 + crow) * H_ + ccol;
            #pragma unroll
            for (int q = 0; q < 2; q++) {
                float4 f0 = __ldcg((const float4*)(src + q * 16));
                float4 f1 = __ldcg((const float4*)(src + q * 16 + 4));
                float4 f2 = __ldcg((const float4*)(src + q * 16 + 8));
                float4 f3 = __ldcg((const float4*)(src + q * 16 + 12));
                *(ull*)&hs[crow * HKS2 + ccol + q * 16]      = cvt4h(f0);
                *(ull*)&hs[crow * HKS2 + ccol + q * 16 + 4]  = cvt4h(f1);
                *(ull*)&hs[crow * HKS2 + ccol + q * 16 + 8]  = cvt4h(f2);
                *(ull*)&hs[crow * HKS2 + ccol + q * 16 + 12] = cvt4h(f3);
            }
        } else {
            const __half* src = g_hs + ((size_t)(t - 1) * B_ + b0 + crow) * H_ + ccol;
            const uint32_t dst = smb + OFF_HS + (crow * HKS2 + ccol) * 2;
            CP_ASYNC16(dst,      src);
            CP_ASYNC16(dst + 16, src + 8);
            CP_ASYNC16(dst + 32, src + 16);
            CP_ASYNC16(dst + 48, src + 24);
            CP_COMMIT();
            CP_WAIT0();
        }
        __syncthreads();

        // ---- mma: this warp's k half (full 256 k)
        float acc[3][4];
        #pragma unroll
        for (int ni = 0; ni < 3; ni++)
            #pragma unroll
            for (int q = 0; q < 4; q++) acc[ni][q] = 0.0f;

        #pragma unroll
        for (int ks = 0; ks < 16; ks++) {
            const int kw2 = (kh * 256 + ks * 16) * 2;
            unsigned wh01[4], wh2[2], ah[4];
            LDSM4(wh01, wH01 + kw2);
            LDSM2(wh2,  wH2 + kw2);
            LDSM4(ah,   hA + kw2);
            mma4(acc[0], ah, wh01[0], wh01[1]);
            mma4(acc[1], ah, wh01[2], wh01[3]);
            mma4(acc[2], ah, wh2[0], wh2[1]);
        }
        __syncthreads();

        // ---- kh1 partials -> gred; kh0 adds + masked in-register gates
        float* gp = &gred[(w7 * 32 + lane) * 12];
        if (kh == 1) {
            #pragma unroll
            for (int ni = 0; ni < 3; ni++)
                #pragma unroll
                for (int q = 0; q < 4; q++) gp[ni * 4 + q] = acc[ni][q];
        }
        __syncthreads();

        if (kh == 0) {
            #pragma unroll
            for (int ni = 0; ni < 3; ni++)
                #pragma unroll
                for (int q = 0; q < 4; q++) acc[ni][q] += gp[ni * 4 + q];

            #pragma unroll
            for (int mrow = 0; mrow < 2; mrow++) {
                const int b = b0 + wm + g + 8 * mrow;
                const float me = mrow ? me1 : me0;
                const float2 pv = mrow ? prev1 : prev0;
                const float2 ir = mrow ? ir1 : ir0;
                const float2 iz = mrow ? iz1 : iz0;
                const float2 in_ = mrow ? in1 : in0;
                const int q0 = mrow * 2;

                // mask factored: acc scaled by me (scalar per batch row)
                float hm0 = pv.x * me, hm1 = pv.y * me;
                float r0 = 1.0f / (1.0f + __expf(-(ir.x + me * acc[0][q0])));
                float r1 = 1.0f / (1.0f + __expf(-(ir.y + me * acc[0][q0 + 1])));
                float z0 = 1.0f / (1.0f + __expf(-(iz.x + me * acc[1][q0])));
                float z1 = 1.0f / (1.0f + __expf(-(iz.y + me * acc[1][q0 + 1])));
                float e0 = __expf(2.0f * (in_.x + r0 * (me * acc[2][q0] + bh2.x)));
                float e1 = __expf(2.0f * (in_.y + r1 * (me * acc[2][q0 + 1] + bh2.y)));
                float n0 = __fdividef(e0 - 1.0f, e0 + 1.0f);
                float n1 = __fdividef(e1 - 1.0f, e1 + 1.0f);

                float2 out;
                out.x = (1.0f - z0) * n0 + z0 * hm0;
                out.y = (1.0f - z1) * n1 + z1 * hm1;
                *(float2*)(ys + ((size_t)t * B_ + b) * H_ + eh2) = out;
                // fp16 copy for next step's cp.async consumers
                __half2 oh = __floats2half2_rn(out.x, out.y);
                *(__half2*)(g_hs + ((size_t)t * B_ + b) * H_ + eh2) = oh;
                if (mrow) prev1 = out; else prev0 = out;
            }
        }
        __syncthreads();

        // ---- release: this tile of step t is visible
        if (tid == 0) {
            __threadfence();
            *myflag = t + 1;
        }
    }
}

// ===========================================================================
extern "C" void kernel_launch(void* const* d_in, const int* in_sizes, int n_in,
                              void* d_out, int out_size)
{
    const float* rnn_state = (const float*)d_in[0];
    const float* ins       = (const float*)d_in[1];
    const void*  resets    = d_in[2];
    const float* Wi        = (const float*)d_in[3];
    const float* bi        = (const float*)d_in[4];
    const float* Whrz      = (const float*)d_in[5];
    const float* Whn       = (const float*)d_in[6];
    const float* bhn       = (const float*)d_in[7];

    float* final_h = (float*)d_out;
    float* ys      = (float*)d_out + (size_t)B_ * H_;

    float* gi_ptr = nullptr;
    cudaGetSymbolAddress((void**)&gi_ptr, g_gi);

    cudaFuncSetAttribute(gru_scan_kernel,
                         cudaFuncAttributeMaxDynamicSharedMemorySize, SCAN_SMEM);

    prep_mask_kernel<<<1, 1024>>>(resets);               // launch #3
    conv_ab_kernel<<<2048, 256>>>(ins, Wi);              // launch #4
    gi_gemm_kernel<<<dim3(H3_ / 128, (T_ * B_) / 128), 256>>>(bi, gi_ptr);  // #5
    gru_scan_kernel<<<NBLK, SNTHR, SCAN_SMEM>>>(rnn_state, Whrz, Whn, bhn,
                                                gi_ptr, ys);                // #6
    cudaMemcpyAsync(final_h, ys + (size_t)(T_ - 1) * B_ * H_,
                    (size_t)B_ * H_ * sizeof(float),
                    cudaMemcpyDeviceToDevice, 0);
}